// round 14
// baseline (speedup 1.0000x reference)
#include <cuda_runtime.h>
#include <cuda_bf16.h>
#include <cuda_fp16.h>
#include <cstdint>

#define Nn 16384
#define Ne 65536
#define Dd 64
#define Hh 128
#define Ll 3
#define Gg 512
#define Oo 128
#define CHUNK 4096   // nodes per q_mma/msg2 interleave chunk (Q slice = 64MB <= L2)

// ---------------- scratch -------------------------------------------------------
__device__ float g_x[Nn*Dd];
__device__ float g_h[Nn*Dd];
__device__ __half g_h16[Nn*Dd];
__device__ float g_y2[Nn*Dd];
__device__ float g_a[(size_t)Ne*Hh];
__device__ __half g_Q[(size_t)Nn*Hh*Dd];                 // [n][k][f], fp16, 256 MB
__device__ __half g_w2t[(size_t)Ll*Hh*Dd*Dd];           // [l][k][f][d] fp16
__device__ __half g_w1t[(size_t)Ll*Hh*Dd];              // [l][f=128][d=64] fp16
__device__ __half g_ea16[(size_t)Ne*Dd];
__device__ float g_num[Nn*Dd];
__device__ float g_deg[Nn];
__device__ float g_pool[Gg*Dd];
__device__ float g_cnt[Gg];
// CSR by src
__device__ int g_srccnt[Nn];
__device__ int g_cursor[Nn];
__device__ int g_rowptr[Nn + 1];
__device__ int g_edst[Ne];
__device__ int g_eidx[Ne];

__device__ __forceinline__ float leaky(float v){ return v > 0.f ? v : 0.01f*v; }

// ---------------- merged weight/edge prep ------------------------------------------
__global__ void k_prep(const float* __restrict__ W2, const float* __restrict__ W1,
                       const float* __restrict__ ea){
    int idx = blockIdx.x*blockDim.x + threadIdx.x;
    if(idx < Ne*Dd){
        g_ea16[idx] = __float2half(ea[idx]);
    }
    if(idx < Ll*Hh*Dd*Dd){
        int lk = idx >> 12;
        int d = (idx >> 6) & 63;
        int f = idx & 63;
        g_w2t[(size_t)lk*4096 + f*64 + d] = __float2half(W2[idx]);
    }
    if(idx < Ll*Dd*Hh){
        int l = idx >> 13;
        int d = (idx >> 7) & 63;
        int f = idx & 127;
        g_w1t[(size_t)l*Hh*Dd + f*64 + d] = __float2half(W1[idx]);
    }
}

// ---------------- init --------------------------------------------------------------
__global__ void k_init(const float* __restrict__ x){
    int i = blockIdx.x*blockDim.x + threadIdx.x;
    if(i < Nn*Dd){ g_x[i] = x[i]; g_num[i] = 0.f; }
    if(i < Gg*Dd) g_pool[i] = 0.f;
    if(i < Nn){ g_deg[i] = 0.f; g_srccnt[i] = 0; g_cursor[i] = 0; }
    if(i < Gg)  g_cnt[i] = 0.f;
}

__global__ void k_degcnt(const int* __restrict__ ei, const int* __restrict__ batch){
    int i = blockIdx.x*blockDim.x + threadIdx.x;
    if(i < Ne){
        atomicAdd(&g_deg[ei[Ne + i]], 1.f);
        atomicAdd(&g_srccnt[ei[i]], 1);
    }
    if(i < Nn) atomicAdd(&g_cnt[batch[i]], 1.f);
}

// single-block exclusive scan of g_srccnt -> g_rowptr
__global__ void k_scan(){
    __shared__ int wsum[32];
    int t = threadIdx.x;
    int base = t*16;
    int c[16]; int s = 0;
    #pragma unroll
    for(int i = 0; i < 16; i++){ c[i] = g_srccnt[base + i]; s += c[i]; }
    int lane = t & 31, w = t >> 5;
    int v = s;
    #pragma unroll
    for(int o = 1; o < 32; o <<= 1){ int u = __shfl_up_sync(~0u, v, o); if(lane >= o) v += u; }
    if(lane == 31) wsum[w] = v;
    __syncthreads();
    if(w == 0){
        int x = wsum[lane];
        #pragma unroll
        for(int o = 1; o < 32; o <<= 1){ int u = __shfl_up_sync(~0u, x, o); if(lane >= o) x += u; }
        wsum[lane] = x;
    }
    __syncthreads();
    int run = v - s + (w > 0 ? wsum[w-1] : 0);
    #pragma unroll
    for(int i = 0; i < 16; i++){ g_rowptr[base + i] = run; run += c[i]; }
    if(t == 1023) g_rowptr[Nn] = run;
}

__global__ void k_fill(const int* __restrict__ ei){
    int e = blockIdx.x*blockDim.x + threadIdx.x;
    if(e >= Ne) return;
    int src = ei[e];
    int pos = g_rowptr[src] + atomicAdd(&g_cursor[src], 1);
    g_edst[pos] = ei[Ne + e];
    g_eidx[pos] = e;
}

// ---------------- h = leaky(LN(x)); also emit fp16 ----------------------------------
__global__ void k_ln(const float* __restrict__ sc, const float* __restrict__ bi){
    int lane = threadIdx.x & 31, w = threadIdx.x >> 5;
    int n = blockIdx.x*8 + w;
    float v0 = g_x[n*64 + lane], v1 = g_x[n*64 + 32 + lane];
    float s = v0 + v1;
    #pragma unroll
    for(int o = 16; o; o >>= 1) s += __shfl_xor_sync(0xffffffffu, s, o);
    float mu = s * 0.015625f;
    float d0 = v0 - mu, d1 = v1 - mu;
    float q = d0*d0 + d1*d1;
    #pragma unroll
    for(int o = 16; o; o >>= 1) q += __shfl_xor_sync(0xffffffffu, q, o);
    float r = rsqrtf(q * 0.015625f + 1e-5f);
    float h0 = leaky(d0*r*sc[lane]      + bi[lane]);
    float h1 = leaky(d1*r*sc[32 + lane] + bi[32 + lane]);
    g_h[n*64 + lane]      = h0;
    g_h[n*64 + 32 + lane] = h1;
    g_h16[n*64 + lane]      = __float2half(h0);
    g_h16[n*64 + 32 + lane] = __float2half(h1);
}

// ---------------- mma helpers --------------------------------------------------------
#define BPAD 72
__device__ __forceinline__ void mma_f16(float* c, const uint32_t* a, uint32_t b0, uint32_t b1){
    asm volatile(
        "mma.sync.aligned.m16n8k16.row.col.f32.f16.f16.f32 "
        "{%0,%1,%2,%3}, {%4,%5,%6,%7}, {%8,%9}, {%0,%1,%2,%3};"
        : "+f"(c[0]), "+f"(c[1]), "+f"(c[2]), "+f"(c[3])
        : "r"(a[0]), "r"(a[1]), "r"(a[2]), "r"(a[3]), "r"(b0), "r"(b1));
}
__device__ __forceinline__ void ldsm_x4(uint32_t& r0, uint32_t& r1, uint32_t& r2, uint32_t& r3,
                                        uint32_t addr){
    asm volatile("ldmatrix.sync.aligned.m8n8.x4.shared.b16 {%0,%1,%2,%3}, [%4];"
        : "=r"(r0), "=r"(r1), "=r"(r2), "=r"(r3) : "r"(addr));
}

__device__ __forceinline__ void load_a_f16(const __half* p, int m0, int g, int tq,
                                           uint32_t a[4][4]){
    int r0 = (m0 + g)*64, r1 = (m0 + g + 8)*64;
    #pragma unroll
    for(int ks = 0; ks < 4; ks++){
        int c0 = ks*16 + 2*tq, c1 = c0 + 8;
        a[ks][0] = *(const uint32_t*)&p[r0 + c0];
        a[ks][1] = *(const uint32_t*)&p[r1 + c0];
        a[ks][2] = *(const uint32_t*)&p[r0 + c1];
        a[ks][3] = *(const uint32_t*)&p[r1 + c1];
    }
}

// ---------------- a = leaky(ea @ W1 + b1), pure fp16 1-term --------------------------
__global__ __launch_bounds__(256) void k_emlp_mma(int layer, const float* __restrict__ b1l){
    __shared__ __align__(16) __half Bs[128*BPAD];
    const __half* w1 = g_w1t + (size_t)layer*Hh*Dd;
    int tid = threadIdx.x, w = tid >> 5, lane = tid & 31;
    int g = lane >> 2, tq = lane & 3;
    int e0 = blockIdx.x * 128;
    int m0 = e0 + w*16;

    uint32_t af[4][4];
    load_a_f16(g_ea16, m0, g, tq, af);
    {
        const uint4* sw = (const uint4*)w1;
        #pragma unroll
        for(int i = 0; i < 4; i++){
            int idx = i*256 + tid;
            int f = idx >> 3, u = idx & 7;
            *(uint4*)&Bs[f*BPAD + u*8] = sw[idx];
        }
    }
    __syncthreads();

    float acc[16][4];
    #pragma unroll
    for(int j = 0; j < 16; j++)
        #pragma unroll
        for(int i = 0; i < 4; i++) acc[j][i] = 0.f;

    #pragma unroll
    for(int ks = 0; ks < 4; ks++){
        int cb0 = ks*16 + 2*tq, cb1 = cb0 + 8;
        #pragma unroll
        for(int j = 0; j < 16; j++){
            int row = (j*8 + g)*BPAD;
            uint32_t b0 = *(const uint32_t*)&Bs[row + cb0];
            uint32_t b1 = *(const uint32_t*)&Bs[row + cb1];
            mma_f16(acc[j], af[ks], b0, b1);
        }
    }

    float* a0 = g_a + (size_t)(m0 + g)*128;
    float* a1 = g_a + (size_t)(m0 + g + 8)*128;
    #pragma unroll
    for(int j = 0; j < 16; j++){
        int c = j*8 + 2*tq;
        float2 bb = *(const float2*)&b1l[c];
        *(float2*)&a0[c] = make_float2(leaky(acc[j][0] + bb.x), leaky(acc[j][1] + bb.y));
        *(float2*)&a1[c] = make_float2(leaky(acc[j][2] + bb.x), leaky(acc[j][3] + bb.y));
    }
}

// ---------------- Q via mma v5 (chunked): pure fp16 1-term ---------------------------
#define DPAD 72
__global__ __launch_bounds__(256, 2) void k_q_mma(int layer, int nbase){
    __shared__ __align__(16) char smem_raw[18432];
    __half* Bh = (__half*)smem_raw;              // 64*BPAD*2 = 9216 B
    __half* Ds = (__half*)smem_raw;              // 8 warps * 16 * DPAD * 2 = 18432 B
    const __half* w2 = g_w2t + (size_t)layer*Hh*4096;
    int tid = threadIdx.x, w = tid >> 5, lane = tid & 31;
    int g = lane >> 2, tq = lane & 3;
    int n0 = nbase + blockIdx.x * 256;
    int m0 = n0 + w*32;

    uint32_t a0f[4][4], a1f[4][4];
    load_a_f16(g_h16, m0,      g, tq, a0f);
    load_a_f16(g_h16, m0 + 16, g, tq, a1f);

    int sel = lane >> 3, rw = lane & 7;
    uint32_t lds_base = (uint32_t)__cvta_generic_to_shared(
        &Bh[rw*BPAD + (sel & 1)*8 + (sel >> 1)*16]);

    int kbase = blockIdx.y*8;
    uint4 pf0, pf1;
    {
        const uint4* sw = (const uint4*)(w2 + (size_t)kbase*4096);
        pf0 = sw[tid]; pf1 = sw[256 + tid];
    }
    int f0 = tid >> 3,         u0 = tid & 7;
    int f1 = (256 + tid) >> 3, u1 = tid & 7;

    __half* ds = Ds + w*16*DPAD;

    for(int kk = 0; kk < 8; kk++){
        int k = kbase + kk;
        __syncthreads();
        *(uint4*)&Bh[f0*BPAD + u0*8] = pf0;
        *(uint4*)&Bh[f1*BPAD + u1*8] = pf1;
        if(kk < 7){
            const uint4* sw = (const uint4*)(w2 + (size_t)(k + 1)*4096);
            pf0 = sw[tid]; pf1 = sw[256 + tid];
        }
        __syncthreads();

        float acc0[8][4], acc1[8][4];
        #pragma unroll
        for(int j = 0; j < 8; j++)
            #pragma unroll
            for(int i = 0; i < 4; i++){ acc0[j][i] = 0.f; acc1[j][i] = 0.f; }

        #pragma unroll
        for(int ksp = 0; ksp < 2; ksp++){
            #pragma unroll
            for(int j = 0; j < 8; j++){
                uint32_t b00, b01, b10, b11;
                ldsm_x4(b00, b01, b10, b11,
                        lds_base + (uint32_t)((j*8*BPAD + ksp*32)*2));
                mma_f16(acc0[j], a0f[2*ksp],     b00, b01);
                mma_f16(acc0[j], a0f[2*ksp + 1], b10, b11);
                mma_f16(acc1[j], a1f[2*ksp],     b00, b01);
                mma_f16(acc1[j], a1f[2*ksp + 1], b10, b11);
            }
        }
        __syncthreads();

        #pragma unroll
        for(int j = 0; j < 8; j++){
            int c = j*8 + 2*tq;
            *(__half2*)&ds[g*DPAD + c]       = __floats2half2_rn(acc0[j][0], acc0[j][1]);
            *(__half2*)&ds[(g + 8)*DPAD + c] = __floats2half2_rn(acc0[j][2], acc0[j][3]);
        }
        __syncwarp();
        #pragma unroll
        for(int i = 0; i < 4; i++){
            int idx = i*32 + lane;
            int r = idx >> 3, u = idx & 7;
            uint4 v = *(const uint4*)&ds[r*DPAD + u*8];
            *(uint4*)(g_Q + ((size_t)(m0 + r)*128 + k)*64 + u*8) = v;
        }
        __syncwarp();
        #pragma unroll
        for(int j = 0; j < 8; j++){
            int c = j*8 + 2*tq;
            *(__half2*)&ds[g*DPAD + c]       = __floats2half2_rn(acc1[j][0], acc1[j][1]);
            *(__half2*)&ds[(g + 8)*DPAD + c] = __floats2half2_rn(acc1[j][2], acc1[j][3]);
        }
        __syncwarp();
        #pragma unroll
        for(int i = 0; i < 4; i++){
            int idx = i*32 + lane;
            int r = idx >> 3, u = idx & 7;
            uint4 v = *(const uint4*)&ds[r*DPAD + u*8];
            *(uint4*)(g_Q + ((size_t)(m0 + 16 + r)*128 + k)*64 + u*8) = v;
        }
    }
}

// ---------------- messages v4: 128 threads, 4 edge slots (avg degree ~4) -------------
__global__ __launch_bounds__(128) void k_msg2(int nbase){
    __shared__ __align__(16) __half Qs[8192];   // [k][f] fp16, 16KB
    __shared__ float as[4][128];
    __shared__ float y2s[64];
    int n = nbase + blockIdx.x;
    int beg = g_rowptr[n], end = g_rowptr[n+1];
    if(beg == end) return;
    int tid = threadIdx.x;
    const uint4* qsrc = (const uint4*)(g_Q + (size_t)n*8192);
    uint4* qd = (uint4*)Qs;
    #pragma unroll
    for(int i = 0; i < 8; i++) qd[i*128 + tid] = qsrc[i*128 + tid];
    if(tid < 64) y2s[tid] = g_y2[n*64 + tid];
    __syncthreads();
    int g = tid >> 5, lane = tid & 31;
    const __half2* Q2 = (const __half2*)Qs;
    for(int base = beg; base < end; base += 4){
        #pragma unroll
        for(int i = 0; i < 4; i++){
            int idx = i*128 + tid;
            int el = idx >> 7, k = idx & 127;
            int j = base + el;
            if(j < end) as[el][k] = g_a[(size_t)g_eidx[j]*128 + k];
        }
        __syncthreads();
        int j = base + g;
        if(j < end){
            int dst = g_edst[j];
            float accx = y2s[2*lane], accy = y2s[2*lane + 1];
            #pragma unroll 8
            for(int k4 = 0; k4 < 128; k4 += 4){
                float4 av = *(const float4*)&as[g][k4];
                float2 q0 = __half22float2(Q2[(k4+0)*32 + lane]);
                float2 q1 = __half22float2(Q2[(k4+1)*32 + lane]);
                float2 q2 = __half22float2(Q2[(k4+2)*32 + lane]);
                float2 q3 = __half22float2(Q2[(k4+3)*32 + lane]);
                accx = fmaf(av.x, q0.x, accx); accy = fmaf(av.x, q0.y, accy);
                accx = fmaf(av.y, q1.x, accx); accy = fmaf(av.y, q1.y, accy);
                accx = fmaf(av.z, q2.x, accx); accy = fmaf(av.z, q2.y, accy);
                accx = fmaf(av.w, q3.x, accx); accy = fmaf(av.w, q3.y, accy);
            }
            atomicAdd(&g_num[dst*64 + 2*lane],     accx);
            atomicAdd(&g_num[dst*64 + 2*lane + 1], accy);
        }
        __syncthreads();
    }
}

// ---------------- shared 64x64 small GEMM with three epilogues -----------------------
__global__ __launch_bounds__(256) void k_nn64(const float* __restrict__ B,
                                              const float* __restrict__ bias,
                                              const float* __restrict__ cb,
                                              const int* __restrict__ batch,
                                              int mode){
    __shared__ float As[64][64];
    __shared__ float Bs[64][64];
    const float* A = (mode == 2) ? g_x : g_h;
    int tid = threadIdx.x;
    int n0 = blockIdx.x * 64;
    #pragma unroll
    for(int i = 0; i < 4; i++){
        int idx = i*256 + tid; int m = idx >> 4, d = (idx & 15) * 4;
        *(float4*)&As[m][d] = *(const float4*)&A[(size_t)(n0 + m)*64 + d];
        *(float4*)&Bs[m][d] = *(const float4*)&B[(size_t)m*64 + d];
    }
    __syncthreads();
    int tx = tid & 15, ty = tid >> 4;
    float acc[4][4];
    #pragma unroll
    for(int i = 0; i < 4; i++)
        #pragma unroll
        for(int j = 0; j < 4; j++) acc[i][j] = 0.f;

    #pragma unroll 4
    for(int d4 = 0; d4 < 64; d4 += 4){
        float4 a[4];
        #pragma unroll
        for(int i = 0; i < 4; i++) a[i] = *(float4*)&As[ty*4 + i][d4];
        #pragma unroll
        for(int dd = 0; dd < 4; dd++){
            float4 bv = *(float4*)&Bs[d4 + dd][tx*4];
            #pragma unroll
            for(int i = 0; i < 4; i++){
                float av = (dd==0)?a[i].x:(dd==1)?a[i].y:(dd==2)?a[i].z:a[i].w;
                acc[i][0] = fmaf(av, bv.x, acc[i][0]);
                acc[i][1] = fmaf(av, bv.y, acc[i][1]);
                acc[i][2] = fmaf(av, bv.z, acc[i][2]);
                acc[i][3] = fmaf(av, bv.w, acc[i][3]);
            }
        }
    }
    if(mode == 0){
        #pragma unroll
        for(int i = 0; i < 4; i++){
            float4 o; o.x = acc[i][0]; o.y = acc[i][1]; o.z = acc[i][2]; o.w = acc[i][3];
            *(float4*)&g_y2[(size_t)(n0 + ty*4 + i)*64 + tx*4] = o;
        }
    } else if(mode == 1){
        #pragma unroll
        for(int i = 0; i < 4; i++){
            int n = n0 + ty*4 + i;
            float inv = 1.f / fmaxf(g_deg[n], 1.f);
            #pragma unroll
            for(int j = 0; j < 4; j++){
                int idx = n*64 + tx*4 + j;
                float v = g_x[idx] + g_num[idx]*inv + acc[i][j] + cb[tx*4 + j];
                g_x[idx] = v;
                g_num[idx] = 0.f;
            }
        }
    } else {
        #pragma unroll
        for(int i = 0; i < 4; i++){
            int n = n0 + ty*4 + i;
            int b = batch[n];
            #pragma unroll
            for(int j = 0; j < 4; j++)
                atomicAdd(&g_pool[b*64 + tx*4 + j], acc[i][j] + bias[tx*4 + j]);
        }
    }
}

// ---------------- head ----------------------------------------------------------------
__global__ void k_out(const float* __restrict__ oW, const float* __restrict__ ob,
                      float* __restrict__ out){
    __shared__ float p[64];
    int g = blockIdx.x, t = threadIdx.x;
    if(t < 64){
        float c = fmaxf(g_cnt[g], 1.f);
        p[t] = leaky(g_pool[g*64 + t] / c);
    }
    __syncthreads();
    float acc = ob[t];
    #pragma unroll 8
    for(int f = 0; f < 64; f++)
        acc = fmaf(p[f], oW[f*128 + t], acc);
    out[g*128 + t] = acc;
}

// ---------------- launch ----------------------------------------------------------------
extern "C" void kernel_launch(void* const* d_in, const int* in_sizes, int n_in,
                              void* d_out, int out_size){
    const float* x    = (const float*)d_in[0];
    const int*   ei   = (const int*)  d_in[1];
    const float* ea   = (const float*)d_in[2];
    const int*   batch= (const int*)  d_in[3];
    const float* lns  = (const float*)d_in[4];
    const float* lnb  = (const float*)d_in[5];
    const float* W1   = (const float*)d_in[6];
    const float* b1   = (const float*)d_in[7];
    const float* W2   = (const float*)d_in[8];
    const float* b2   = (const float*)d_in[9];
    const float* root = (const float*)d_in[10];
    const float* cb   = (const float*)d_in[11];
    const float* dW   = (const float*)d_in[12];
    const float* db   = (const float*)d_in[13];
    const float* oW   = (const float*)d_in[14];
    const float* ob   = (const float*)d_in[15];
    float* out = (float*)d_out;

    dim3 gqc(CHUNK/256, Hh/8);   // 16 x 16 = 256 CTAs per chunk

    // Launch index 3 (ncu capture slot) = k_q_mma(layer 0, chunk 0).
    k_prep<<<(Ne*Dd + 255)/256, 256>>>(W2, W1, ea);            // 0
    k_init<<<(Nn*Dd + 255)/256, 256>>>(x);                     // 1
    k_ln<<<Nn/8, 256>>>(lns, lnb);                             // 2
    k_q_mma<<<gqc, 256>>>(0, 0);                               // 3  <- profiled
    k_degcnt<<<(Ne + 255)/256, 256>>>(ei, batch);              // 4
    k_scan<<<1, 1024>>>();                                     // 5
    k_fill<<<(Ne + 255)/256, 256>>>(ei);                       // 6
    k_emlp_mma<<<Ne/128, 256>>>(0, b1);                        // 7
    k_nn64<<<Nn/64, 256>>>(b2, nullptr, nullptr, nullptr, 0);  // 8: y2 = h@B2
    k_msg2<<<CHUNK, 128>>>(0);                                 // 9  (consumes chunk 0)
    for(int c = 1; c < Nn/CHUNK; c++){                         // producer/consumer pairs
        k_q_mma<<<gqc, 256>>>(0, c*CHUNK);
        k_msg2<<<CHUNK, 128>>>(c*CHUNK);
    }
    k_nn64<<<Nn/64, 256>>>(root, nullptr, cb, nullptr, 1);

    for(int l = 1; l < Ll; l++){
        k_ln<<<Nn/8, 256>>>(lns + l*64, lnb + l*64);
        k_emlp_mma<<<Ne/128, 256>>>(l, b1 + (size_t)l*128);
        k_nn64<<<Nn/64, 256>>>(b2 + (size_t)l*4096, nullptr, nullptr, nullptr, 0);
        for(int c = 0; c < Nn/CHUNK; c++){
            k_q_mma<<<gqc, 256>>>(l, c*CHUNK);
            k_msg2<<<CHUNK, 128>>>(c*CHUNK);
        }
        k_nn64<<<Nn/64, 256>>>(root + (size_t)l*4096, nullptr, cb + (size_t)l*64, nullptr, 1);
    }

    k_nn64<<<Nn/64, 256>>>(dW, db, nullptr, batch, 2);  // dense + pool
    k_out<<<Gg, 128>>>(oW, ob, out);
}

// round 15
// speedup vs baseline: 1.1502x; 1.1502x over previous
#include <cuda_runtime.h>
#include <cuda_bf16.h>
#include <cuda_fp16.h>
#include <cstdint>

#define Nn 16384
#define Ne 65536
#define Dd 64
#define Hh 128
#define Ll 3
#define Gg 512
#define Oo 128

// ---------------- scratch -------------------------------------------------------
__device__ float g_x[Nn*Dd];
__device__ float g_h[Nn*Dd];
__device__ __half g_h16[Nn*Dd];
__device__ float g_y2[Nn*Dd];
__device__ float g_a[(size_t)Ne*Hh];
__device__ __half g_Q[(size_t)Nn*Hh*Dd];                 // [n][k][f], fp16, 256 MB
__device__ __half g_w2t[(size_t)Ll*Hh*Dd*Dd];           // [l][k][f][d] fp16
__device__ __half g_w1t[(size_t)Ll*Hh*Dd];              // [l][f=128][d=64] fp16
__device__ __half g_ea16[(size_t)Ne*Dd];
__device__ float g_num[Nn*Dd];
__device__ float g_deg[Nn];
__device__ float g_pool[Gg*Dd];
__device__ float g_cnt[Gg];
// CSR by src
__device__ int g_srccnt[Nn];
__device__ int g_cursor[Nn];
__device__ int g_rowptr[Nn + 1];
__device__ int g_edst[Ne];
__device__ int g_eidx[Ne];

__device__ __forceinline__ float leaky(float v){ return v > 0.f ? v : 0.01f*v; }

// ---------------- merged weight/edge prep ------------------------------------------
__global__ void k_prep(const float* __restrict__ W2, const float* __restrict__ W1,
                       const float* __restrict__ ea){
    int idx = blockIdx.x*blockDim.x + threadIdx.x;
    if(idx < Ne*Dd){
        g_ea16[idx] = __float2half(ea[idx]);
    }
    if(idx < Ll*Hh*Dd*Dd){
        int lk = idx >> 12;
        int d = (idx >> 6) & 63;
        int f = idx & 63;
        g_w2t[(size_t)lk*4096 + f*64 + d] = __float2half(W2[idx]);
    }
    if(idx < Ll*Dd*Hh){
        int l = idx >> 13;
        int d = (idx >> 7) & 63;
        int f = idx & 127;
        g_w1t[(size_t)l*Hh*Dd + f*64 + d] = __float2half(W1[idx]);
    }
}

// ---------------- init --------------------------------------------------------------
__global__ void k_init(const float* __restrict__ x){
    int i = blockIdx.x*blockDim.x + threadIdx.x;
    if(i < Nn*Dd){ g_x[i] = x[i]; g_num[i] = 0.f; }
    if(i < Gg*Dd) g_pool[i] = 0.f;
    if(i < Nn){ g_deg[i] = 0.f; g_srccnt[i] = 0; g_cursor[i] = 0; }
    if(i < Gg)  g_cnt[i] = 0.f;
}

__global__ void k_degcnt(const int* __restrict__ ei, const int* __restrict__ batch){
    int i = blockIdx.x*blockDim.x + threadIdx.x;
    if(i < Ne){
        atomicAdd(&g_deg[ei[Ne + i]], 1.f);
        atomicAdd(&g_srccnt[ei[i]], 1);
    }
    if(i < Nn) atomicAdd(&g_cnt[batch[i]], 1.f);
}

// single-block exclusive scan of g_srccnt -> g_rowptr
__global__ void k_scan(){
    __shared__ int wsum[32];
    int t = threadIdx.x;
    int base = t*16;
    int c[16]; int s = 0;
    #pragma unroll
    for(int i = 0; i < 16; i++){ c[i] = g_srccnt[base + i]; s += c[i]; }
    int lane = t & 31, w = t >> 5;
    int v = s;
    #pragma unroll
    for(int o = 1; o < 32; o <<= 1){ int u = __shfl_up_sync(~0u, v, o); if(lane >= o) v += u; }
    if(lane == 31) wsum[w] = v;
    __syncthreads();
    if(w == 0){
        int x = wsum[lane];
        #pragma unroll
        for(int o = 1; o < 32; o <<= 1){ int u = __shfl_up_sync(~0u, x, o); if(lane >= o) x += u; }
        wsum[lane] = x;
    }
    __syncthreads();
    int run = v - s + (w > 0 ? wsum[w-1] : 0);
    #pragma unroll
    for(int i = 0; i < 16; i++){ g_rowptr[base + i] = run; run += c[i]; }
    if(t == 1023) g_rowptr[Nn] = run;
}

__global__ void k_fill(const int* __restrict__ ei){
    int e = blockIdx.x*blockDim.x + threadIdx.x;
    if(e >= Ne) return;
    int src = ei[e];
    int pos = g_rowptr[src] + atomicAdd(&g_cursor[src], 1);
    g_edst[pos] = ei[Ne + e];
    g_eidx[pos] = e;
}

// ---------------- h = leaky(LN(x)); also emit fp16 ----------------------------------
__global__ void k_ln(const float* __restrict__ sc, const float* __restrict__ bi){
    int lane = threadIdx.x & 31, w = threadIdx.x >> 5;
    int n = blockIdx.x*8 + w;
    float v0 = g_x[n*64 + lane], v1 = g_x[n*64 + 32 + lane];
    float s = v0 + v1;
    #pragma unroll
    for(int o = 16; o; o >>= 1) s += __shfl_xor_sync(0xffffffffu, s, o);
    float mu = s * 0.015625f;
    float d0 = v0 - mu, d1 = v1 - mu;
    float q = d0*d0 + d1*d1;
    #pragma unroll
    for(int o = 16; o; o >>= 1) q += __shfl_xor_sync(0xffffffffu, q, o);
    float r = rsqrtf(q * 0.015625f + 1e-5f);
    float h0 = leaky(d0*r*sc[lane]      + bi[lane]);
    float h1 = leaky(d1*r*sc[32 + lane] + bi[32 + lane]);
    g_h[n*64 + lane]      = h0;
    g_h[n*64 + 32 + lane] = h1;
    g_h16[n*64 + lane]      = __float2half(h0);
    g_h16[n*64 + 32 + lane] = __float2half(h1);
}

// ---------------- mma helpers --------------------------------------------------------
#define BPAD 72
__device__ __forceinline__ void mma_f16(float* c, const uint32_t* a, uint32_t b0, uint32_t b1){
    asm volatile(
        "mma.sync.aligned.m16n8k16.row.col.f32.f16.f16.f32 "
        "{%0,%1,%2,%3}, {%4,%5,%6,%7}, {%8,%9}, {%0,%1,%2,%3};"
        : "+f"(c[0]), "+f"(c[1]), "+f"(c[2]), "+f"(c[3])
        : "r"(a[0]), "r"(a[1]), "r"(a[2]), "r"(a[3]), "r"(b0), "r"(b1));
}
__device__ __forceinline__ void ldsm_x4(uint32_t& r0, uint32_t& r1, uint32_t& r2, uint32_t& r3,
                                        uint32_t addr){
    asm volatile("ldmatrix.sync.aligned.m8n8.x4.shared.b16 {%0,%1,%2,%3}, [%4];"
        : "=r"(r0), "=r"(r1), "=r"(r2), "=r"(r3) : "r"(addr));
}

__device__ __forceinline__ void load_a_f16(const __half* p, int m0, int g, int tq,
                                           uint32_t a[4][4]){
    int r0 = (m0 + g)*64, r1 = (m0 + g + 8)*64;
    #pragma unroll
    for(int ks = 0; ks < 4; ks++){
        int c0 = ks*16 + 2*tq, c1 = c0 + 8;
        a[ks][0] = *(const uint32_t*)&p[r0 + c0];
        a[ks][1] = *(const uint32_t*)&p[r1 + c0];
        a[ks][2] = *(const uint32_t*)&p[r0 + c1];
        a[ks][3] = *(const uint32_t*)&p[r1 + c1];
    }
}

// ---------------- a = leaky(ea @ W1 + b1), pure fp16 1-term --------------------------
__global__ __launch_bounds__(256) void k_emlp_mma(int layer, const float* __restrict__ b1l){
    __shared__ __align__(16) __half Bs[128*BPAD];
    const __half* w1 = g_w1t + (size_t)layer*Hh*Dd;
    int tid = threadIdx.x, w = tid >> 5, lane = tid & 31;
    int g = lane >> 2, tq = lane & 3;
    int e0 = blockIdx.x * 128;
    int m0 = e0 + w*16;

    uint32_t af[4][4];
    load_a_f16(g_ea16, m0, g, tq, af);
    {
        const uint4* sw = (const uint4*)w1;
        #pragma unroll
        for(int i = 0; i < 4; i++){
            int idx = i*256 + tid;
            int f = idx >> 3, u = idx & 7;
            *(uint4*)&Bs[f*BPAD + u*8] = sw[idx];
        }
    }
    __syncthreads();

    float acc[16][4];
    #pragma unroll
    for(int j = 0; j < 16; j++)
        #pragma unroll
        for(int i = 0; i < 4; i++) acc[j][i] = 0.f;

    #pragma unroll
    for(int ks = 0; ks < 4; ks++){
        int cb0 = ks*16 + 2*tq, cb1 = cb0 + 8;
        #pragma unroll
        for(int j = 0; j < 16; j++){
            int row = (j*8 + g)*BPAD;
            uint32_t b0 = *(const uint32_t*)&Bs[row + cb0];
            uint32_t b1 = *(const uint32_t*)&Bs[row + cb1];
            mma_f16(acc[j], af[ks], b0, b1);
        }
    }

    float* a0 = g_a + (size_t)(m0 + g)*128;
    float* a1 = g_a + (size_t)(m0 + g + 8)*128;
    #pragma unroll
    for(int j = 0; j < 16; j++){
        int c = j*8 + 2*tq;
        float2 bb = *(const float2*)&b1l[c];
        *(float2*)&a0[c] = make_float2(leaky(acc[j][0] + bb.x), leaky(acc[j][1] + bb.y));
        *(float2*)&a1[c] = make_float2(leaky(acc[j][2] + bb.x), leaky(acc[j][3] + bb.y));
    }
}

// ---------------- Q via mma v5 (monolithic): pure fp16 1-term ------------------------
#define DPAD 72
__global__ __launch_bounds__(256, 2) void k_q_mma(int layer){
    __shared__ __align__(16) char smem_raw[18432];
    __half* Bh = (__half*)smem_raw;              // 64*BPAD*2 = 9216 B
    __half* Ds = (__half*)smem_raw;              // 8 warps * 16 * DPAD * 2 = 18432 B
    const __half* w2 = g_w2t + (size_t)layer*Hh*4096;
    int tid = threadIdx.x, w = tid >> 5, lane = tid & 31;
    int g = lane >> 2, tq = lane & 3;
    int n0 = blockIdx.x * 256;
    int m0 = n0 + w*32;

    uint32_t a0f[4][4], a1f[4][4];
    load_a_f16(g_h16, m0,      g, tq, a0f);
    load_a_f16(g_h16, m0 + 16, g, tq, a1f);

    int sel = lane >> 3, rw = lane & 7;
    uint32_t lds_base = (uint32_t)__cvta_generic_to_shared(
        &Bh[rw*BPAD + (sel & 1)*8 + (sel >> 1)*16]);

    int kbase = blockIdx.y*8;
    uint4 pf0, pf1;
    {
        const uint4* sw = (const uint4*)(w2 + (size_t)kbase*4096);
        pf0 = sw[tid]; pf1 = sw[256 + tid];
    }
    int f0 = tid >> 3,         u0 = tid & 7;
    int f1 = (256 + tid) >> 3, u1 = tid & 7;

    __half* ds = Ds + w*16*DPAD;

    for(int kk = 0; kk < 8; kk++){
        int k = kbase + kk;
        __syncthreads();
        *(uint4*)&Bh[f0*BPAD + u0*8] = pf0;
        *(uint4*)&Bh[f1*BPAD + u1*8] = pf1;
        if(kk < 7){
            const uint4* sw = (const uint4*)(w2 + (size_t)(k + 1)*4096);
            pf0 = sw[tid]; pf1 = sw[256 + tid];
        }
        __syncthreads();

        float acc0[8][4], acc1[8][4];
        #pragma unroll
        for(int j = 0; j < 8; j++)
            #pragma unroll
            for(int i = 0; i < 4; i++){ acc0[j][i] = 0.f; acc1[j][i] = 0.f; }

        #pragma unroll
        for(int ksp = 0; ksp < 2; ksp++){
            #pragma unroll
            for(int j = 0; j < 8; j++){
                uint32_t b00, b01, b10, b11;
                ldsm_x4(b00, b01, b10, b11,
                        lds_base + (uint32_t)((j*8*BPAD + ksp*32)*2));
                mma_f16(acc0[j], a0f[2*ksp],     b00, b01);
                mma_f16(acc0[j], a0f[2*ksp + 1], b10, b11);
                mma_f16(acc1[j], a1f[2*ksp],     b00, b01);
                mma_f16(acc1[j], a1f[2*ksp + 1], b10, b11);
            }
        }
        __syncthreads();

        #pragma unroll
        for(int j = 0; j < 8; j++){
            int c = j*8 + 2*tq;
            *(__half2*)&ds[g*DPAD + c]       = __floats2half2_rn(acc0[j][0], acc0[j][1]);
            *(__half2*)&ds[(g + 8)*DPAD + c] = __floats2half2_rn(acc0[j][2], acc0[j][3]);
        }
        __syncwarp();
        #pragma unroll
        for(int i = 0; i < 4; i++){
            int idx = i*32 + lane;
            int r = idx >> 3, u = idx & 7;
            uint4 v = *(const uint4*)&ds[r*DPAD + u*8];
            *(uint4*)(g_Q + ((size_t)(m0 + r)*128 + k)*64 + u*8) = v;
        }
        __syncwarp();
        #pragma unroll
        for(int j = 0; j < 8; j++){
            int c = j*8 + 2*tq;
            *(__half2*)&ds[g*DPAD + c]       = __floats2half2_rn(acc1[j][0], acc1[j][1]);
            *(__half2*)&ds[(g + 8)*DPAD + c] = __floats2half2_rn(acc1[j][2], acc1[j][3]);
        }
        __syncwarp();
        #pragma unroll
        for(int i = 0; i < 4; i++){
            int idx = i*32 + lane;
            int r = idx >> 3, u = idx & 7;
            uint4 v = *(const uint4*)&ds[r*DPAD + u*8];
            *(uint4*)(g_Q + ((size_t)(m0 + 16 + r)*128 + k)*64 + u*8) = v;
        }
    }
}

// ---------------- messages v4: 128 threads, 4 edge slots (avg degree ~4) -------------
__global__ __launch_bounds__(128) void k_msg2(){
    __shared__ __align__(16) __half Qs[8192];   // [k][f] fp16, 16KB
    __shared__ float as[4][128];
    __shared__ float y2s[64];
    int n = blockIdx.x;
    int beg = g_rowptr[n], end = g_rowptr[n+1];
    if(beg == end) return;
    int tid = threadIdx.x;
    const uint4* qsrc = (const uint4*)(g_Q + (size_t)n*8192);
    uint4* qd = (uint4*)Qs;
    #pragma unroll
    for(int i = 0; i < 8; i++) qd[i*128 + tid] = qsrc[i*128 + tid];
    if(tid < 64) y2s[tid] = g_y2[n*64 + tid];
    __syncthreads();
    int g = tid >> 5, lane = tid & 31;
    const __half2* Q2 = (const __half2*)Qs;
    for(int base = beg; base < end; base += 4){
        #pragma unroll
        for(int i = 0; i < 4; i++){
            int idx = i*128 + tid;
            int el = idx >> 7, k = idx & 127;
            int j = base + el;
            if(j < end) as[el][k] = g_a[(size_t)g_eidx[j]*128 + k];
        }
        __syncthreads();
        int j = base + g;
        if(j < end){
            int dst = g_edst[j];
            float accx = y2s[2*lane], accy = y2s[2*lane + 1];
            #pragma unroll 8
            for(int k4 = 0; k4 < 128; k4 += 4){
                float4 av = *(const float4*)&as[g][k4];
                float2 q0 = __half22float2(Q2[(k4+0)*32 + lane]);
                float2 q1 = __half22float2(Q2[(k4+1)*32 + lane]);
                float2 q2 = __half22float2(Q2[(k4+2)*32 + lane]);
                float2 q3 = __half22float2(Q2[(k4+3)*32 + lane]);
                accx = fmaf(av.x, q0.x, accx); accy = fmaf(av.x, q0.y, accy);
                accx = fmaf(av.y, q1.x, accx); accy = fmaf(av.y, q1.y, accy);
                accx = fmaf(av.z, q2.x, accx); accy = fmaf(av.z, q2.y, accy);
                accx = fmaf(av.w, q3.x, accx); accy = fmaf(av.w, q3.y, accy);
            }
            atomicAdd(&g_num[dst*64 + 2*lane],     accx);
            atomicAdd(&g_num[dst*64 + 2*lane + 1], accy);
        }
        __syncthreads();
    }
}

// ---------------- shared 64x64 small GEMM with three epilogues -----------------------
__global__ __launch_bounds__(256) void k_nn64(const float* __restrict__ B,
                                              const float* __restrict__ bias,
                                              const float* __restrict__ cb,
                                              const int* __restrict__ batch,
                                              int mode){
    __shared__ float As[64][64];
    __shared__ float Bs[64][64];
    const float* A = (mode == 2) ? g_x : g_h;
    int tid = threadIdx.x;
    int n0 = blockIdx.x * 64;
    #pragma unroll
    for(int i = 0; i < 4; i++){
        int idx = i*256 + tid; int m = idx >> 4, d = (idx & 15) * 4;
        *(float4*)&As[m][d] = *(const float4*)&A[(size_t)(n0 + m)*64 + d];
        *(float4*)&Bs[m][d] = *(const float4*)&B[(size_t)m*64 + d];
    }
    __syncthreads();
    int tx = tid & 15, ty = tid >> 4;
    float acc[4][4];
    #pragma unroll
    for(int i = 0; i < 4; i++)
        #pragma unroll
        for(int j = 0; j < 4; j++) acc[i][j] = 0.f;

    #pragma unroll 4
    for(int d4 = 0; d4 < 64; d4 += 4){
        float4 a[4];
        #pragma unroll
        for(int i = 0; i < 4; i++) a[i] = *(float4*)&As[ty*4 + i][d4];
        #pragma unroll
        for(int dd = 0; dd < 4; dd++){
            float4 bv = *(float4*)&Bs[d4 + dd][tx*4];
            #pragma unroll
            for(int i = 0; i < 4; i++){
                float av = (dd==0)?a[i].x:(dd==1)?a[i].y:(dd==2)?a[i].z:a[i].w;
                acc[i][0] = fmaf(av, bv.x, acc[i][0]);
                acc[i][1] = fmaf(av, bv.y, acc[i][1]);
                acc[i][2] = fmaf(av, bv.z, acc[i][2]);
                acc[i][3] = fmaf(av, bv.w, acc[i][3]);
            }
        }
    }
    if(mode == 0){
        #pragma unroll
        for(int i = 0; i < 4; i++){
            float4 o; o.x = acc[i][0]; o.y = acc[i][1]; o.z = acc[i][2]; o.w = acc[i][3];
            *(float4*)&g_y2[(size_t)(n0 + ty*4 + i)*64 + tx*4] = o;
        }
    } else if(mode == 1){
        #pragma unroll
        for(int i = 0; i < 4; i++){
            int n = n0 + ty*4 + i;
            float inv = 1.f / fmaxf(g_deg[n], 1.f);
            #pragma unroll
            for(int j = 0; j < 4; j++){
                int idx = n*64 + tx*4 + j;
                float v = g_x[idx] + g_num[idx]*inv + acc[i][j] + cb[tx*4 + j];
                g_x[idx] = v;
                g_num[idx] = 0.f;
            }
        }
    } else {
        #pragma unroll
        for(int i = 0; i < 4; i++){
            int n = n0 + ty*4 + i;
            int b = batch[n];
            #pragma unroll
            for(int j = 0; j < 4; j++)
                atomicAdd(&g_pool[b*64 + tx*4 + j], acc[i][j] + bias[tx*4 + j]);
        }
    }
}

// ---------------- head ----------------------------------------------------------------
__global__ void k_out(const float* __restrict__ oW, const float* __restrict__ ob,
                      float* __restrict__ out){
    __shared__ float p[64];
    int g = blockIdx.x, t = threadIdx.x;
    if(t < 64){
        float c = fmaxf(g_cnt[g], 1.f);
        p[t] = leaky(g_pool[g*64 + t] / c);
    }
    __syncthreads();
    float acc = ob[t];
    #pragma unroll 8
    for(int f = 0; f < 64; f++)
        acc = fmaf(p[f], oW[f*128 + t], acc);
    out[g*128 + t] = acc;
}

// ---------------- launch ----------------------------------------------------------------
extern "C" void kernel_launch(void* const* d_in, const int* in_sizes, int n_in,
                              void* d_out, int out_size){
    const float* x    = (const float*)d_in[0];
    const int*   ei   = (const int*)  d_in[1];
    const float* ea   = (const float*)d_in[2];
    const int*   batch= (const int*)  d_in[3];
    const float* lns  = (const float*)d_in[4];
    const float* lnb  = (const float*)d_in[5];
    const float* W1   = (const float*)d_in[6];
    const float* b1   = (const float*)d_in[7];
    const float* W2   = (const float*)d_in[8];
    const float* b2   = (const float*)d_in[9];
    const float* root = (const float*)d_in[10];
    const float* cb   = (const float*)d_in[11];
    const float* dW   = (const float*)d_in[12];
    const float* db   = (const float*)d_in[13];
    const float* oW   = (const float*)d_in[14];
    const float* ob   = (const float*)d_in[15];
    float* out = (float*)d_out;

    dim3 gq(Nn/256, Hh/8);

    // Launch index 3 (ncu capture slot) = k_q_mma(layer 0), monolithic grid.
    k_prep<<<(Ne*Dd + 255)/256, 256>>>(W2, W1, ea);            // 0
    k_init<<<(Nn*Dd + 255)/256, 256>>>(x);                     // 1
    k_ln<<<Nn/8, 256>>>(lns, lnb);                             // 2
    k_q_mma<<<gq, 256>>>(0);                                   // 3  <- profiled
    k_degcnt<<<(Ne + 255)/256, 256>>>(ei, batch);              // 4
    k_scan<<<1, 1024>>>();                                     // 5
    k_fill<<<(Ne + 255)/256, 256>>>(ei);                       // 6
    k_emlp_mma<<<Ne/128, 256>>>(0, b1);                        // 7
    k_nn64<<<Nn/64, 256>>>(b2, nullptr, nullptr, nullptr, 0);  // 8: y2 = h@B2
    k_msg2<<<Nn, 128>>>();                                     // 9
    k_nn64<<<Nn/64, 256>>>(root, nullptr, cb, nullptr, 1);     // 10

    for(int l = 1; l < Ll; l++){
        k_ln<<<Nn/8, 256>>>(lns + l*64, lnb + l*64);
        k_emlp_mma<<<Ne/128, 256>>>(l, b1 + (size_t)l*128);
        k_nn64<<<Nn/64, 256>>>(b2 + (size_t)l*4096, nullptr, nullptr, nullptr, 0);
        k_q_mma<<<gq, 256>>>(l);
        k_msg2<<<Nn, 128>>>();
        k_nn64<<<Nn/64, 256>>>(root + (size_t)l*4096, nullptr, cb + (size_t)l*64, nullptr, 1);
    }

    k_nn64<<<Nn/64, 256>>>(dW, db, nullptr, batch, 2);  // dense + pool
    k_out<<<Gg, 128>>>(oW, ob, out);
}

// round 16
// speedup vs baseline: 1.1852x; 1.0303x over previous
#include <cuda_runtime.h>
#include <cuda_bf16.h>
#include <cuda_fp16.h>
#include <cstdint>

#define Nn 16384
#define Ne 65536
#define Dd 64
#define Hh 128
#define Ll 3
#define Gg 512
#define Oo 128

// ---------------- scratch -------------------------------------------------------
__device__ float g_x[Nn*Dd];
__device__ float g_h[Nn*Dd];
__device__ __half g_h16[Nn*Dd];
__device__ float g_y2[Nn*Dd];
__device__ __half g_a16[(size_t)Ne*Hh];                  // edge MLP out, fp16
__device__ __half g_Q[(size_t)Nn*Hh*Dd];                 // [n][k][f], fp16, 256 MB
__device__ __half g_w2t[(size_t)Ll*Hh*Dd*Dd];           // [l][k][f][d] fp16
__device__ __half g_w1t[(size_t)Ll*Hh*Dd];              // [l][f=128][d=64] fp16
__device__ __half g_ea16[(size_t)Ne*Dd];
__device__ float g_num[Nn*Dd];
__device__ float g_deg[Nn];
__device__ float g_pool[Gg*Dd];
__device__ float g_cnt[Gg];
// CSR by src
__device__ int g_srccnt[Nn];
__device__ int g_cursor[Nn];
__device__ int g_rowptr[Nn + 1];
__device__ int g_edst[Ne];
__device__ int g_eidx[Ne];

__device__ __forceinline__ float leaky(float v){ return v > 0.f ? v : 0.01f*v; }

// ---------------- merged weight/edge prep ------------------------------------------
__global__ void k_prep(const float* __restrict__ W2, const float* __restrict__ W1,
                       const float* __restrict__ ea){
    int idx = blockIdx.x*blockDim.x + threadIdx.x;
    if(idx < Ne*Dd){
        g_ea16[idx] = __float2half(ea[idx]);
    }
    if(idx < Ll*Hh*Dd*Dd){
        int lk = idx >> 12;
        int d = (idx >> 6) & 63;
        int f = idx & 63;
        g_w2t[(size_t)lk*4096 + f*64 + d] = __float2half(W2[idx]);
    }
    if(idx < Ll*Dd*Hh){
        int l = idx >> 13;
        int d = (idx >> 7) & 63;
        int f = idx & 127;
        g_w1t[(size_t)l*Hh*Dd + f*64 + d] = __float2half(W1[idx]);
    }
}

// ---------------- init --------------------------------------------------------------
__global__ void k_init(const float* __restrict__ x){
    int i = blockIdx.x*blockDim.x + threadIdx.x;
    if(i < Nn*Dd){ g_x[i] = x[i]; g_num[i] = 0.f; }
    if(i < Gg*Dd) g_pool[i] = 0.f;
    if(i < Nn){ g_deg[i] = 0.f; g_srccnt[i] = 0; g_cursor[i] = 0; }
    if(i < Gg)  g_cnt[i] = 0.f;
}

__global__ void k_degcnt(const int* __restrict__ ei, const int* __restrict__ batch){
    int i = blockIdx.x*blockDim.x + threadIdx.x;
    if(i < Ne){
        atomicAdd(&g_deg[ei[Ne + i]], 1.f);
        atomicAdd(&g_srccnt[ei[i]], 1);
    }
    if(i < Nn) atomicAdd(&g_cnt[batch[i]], 1.f);
}

// single-block exclusive scan of g_srccnt -> g_rowptr
__global__ void k_scan(){
    __shared__ int wsum[32];
    int t = threadIdx.x;
    int base = t*16;
    int c[16]; int s = 0;
    #pragma unroll
    for(int i = 0; i < 16; i++){ c[i] = g_srccnt[base + i]; s += c[i]; }
    int lane = t & 31, w = t >> 5;
    int v = s;
    #pragma unroll
    for(int o = 1; o < 32; o <<= 1){ int u = __shfl_up_sync(~0u, v, o); if(lane >= o) v += u; }
    if(lane == 31) wsum[w] = v;
    __syncthreads();
    if(w == 0){
        int x = wsum[lane];
        #pragma unroll
        for(int o = 1; o < 32; o <<= 1){ int u = __shfl_up_sync(~0u, x, o); if(lane >= o) x += u; }
        wsum[lane] = x;
    }
    __syncthreads();
    int run = v - s + (w > 0 ? wsum[w-1] : 0);
    #pragma unroll
    for(int i = 0; i < 16; i++){ g_rowptr[base + i] = run; run += c[i]; }
    if(t == 1023) g_rowptr[Nn] = run;
}

__global__ void k_fill(const int* __restrict__ ei){
    int e = blockIdx.x*blockDim.x + threadIdx.x;
    if(e >= Ne) return;
    int src = ei[e];
    int pos = g_rowptr[src] + atomicAdd(&g_cursor[src], 1);
    g_edst[pos] = ei[Ne + e];
    g_eidx[pos] = e;
}

// ---------------- h = leaky(LN(x)); also emit fp16 ----------------------------------
__global__ void k_ln(const float* __restrict__ sc, const float* __restrict__ bi){
    int lane = threadIdx.x & 31, w = threadIdx.x >> 5;
    int n = blockIdx.x*8 + w;
    float v0 = g_x[n*64 + lane], v1 = g_x[n*64 + 32 + lane];
    float s = v0 + v1;
    #pragma unroll
    for(int o = 16; o; o >>= 1) s += __shfl_xor_sync(0xffffffffu, s, o);
    float mu = s * 0.015625f;
    float d0 = v0 - mu, d1 = v1 - mu;
    float q = d0*d0 + d1*d1;
    #pragma unroll
    for(int o = 16; o; o >>= 1) q += __shfl_xor_sync(0xffffffffu, q, o);
    float r = rsqrtf(q * 0.015625f + 1e-5f);
    float h0 = leaky(d0*r*sc[lane]      + bi[lane]);
    float h1 = leaky(d1*r*sc[32 + lane] + bi[32 + lane]);
    g_h[n*64 + lane]      = h0;
    g_h[n*64 + 32 + lane] = h1;
    g_h16[n*64 + lane]      = __float2half(h0);
    g_h16[n*64 + 32 + lane] = __float2half(h1);
}

// ---------------- mma helpers --------------------------------------------------------
#define BPAD 72
__device__ __forceinline__ void mma_f16(float* c, const uint32_t* a, uint32_t b0, uint32_t b1){
    asm volatile(
        "mma.sync.aligned.m16n8k16.row.col.f32.f16.f16.f32 "
        "{%0,%1,%2,%3}, {%4,%5,%6,%7}, {%8,%9}, {%0,%1,%2,%3};"
        : "+f"(c[0]), "+f"(c[1]), "+f"(c[2]), "+f"(c[3])
        : "r"(a[0]), "r"(a[1]), "r"(a[2]), "r"(a[3]), "r"(b0), "r"(b1));
}
__device__ __forceinline__ void ldsm_x4(uint32_t& r0, uint32_t& r1, uint32_t& r2, uint32_t& r3,
                                        uint32_t addr){
    asm volatile("ldmatrix.sync.aligned.m8n8.x4.shared.b16 {%0,%1,%2,%3}, [%4];"
        : "=r"(r0), "=r"(r1), "=r"(r2), "=r"(r3) : "r"(addr));
}
__device__ __forceinline__ void ldsm_x4_t(uint32_t& r0, uint32_t& r1, uint32_t& r2, uint32_t& r3,
                                          uint32_t addr){
    asm volatile("ldmatrix.sync.aligned.m8n8.x4.trans.shared.b16 {%0,%1,%2,%3}, [%4];"
        : "=r"(r0), "=r"(r1), "=r"(r2), "=r"(r3) : "r"(addr));
}

__device__ __forceinline__ void load_a_f16(const __half* p, int m0, int g, int tq,
                                           uint32_t a[4][4]){
    int r0 = (m0 + g)*64, r1 = (m0 + g + 8)*64;
    #pragma unroll
    for(int ks = 0; ks < 4; ks++){
        int c0 = ks*16 + 2*tq, c1 = c0 + 8;
        a[ks][0] = *(const uint32_t*)&p[r0 + c0];
        a[ks][1] = *(const uint32_t*)&p[r1 + c0];
        a[ks][2] = *(const uint32_t*)&p[r0 + c1];
        a[ks][3] = *(const uint32_t*)&p[r1 + c1];
    }
}

// ---------------- a = leaky(ea @ W1 + b1), pure fp16; OUTPUT fp16 --------------------
__global__ __launch_bounds__(256) void k_emlp_mma(int layer, const float* __restrict__ b1l){
    __shared__ __align__(16) __half Bs[128*BPAD];
    const __half* w1 = g_w1t + (size_t)layer*Hh*Dd;
    int tid = threadIdx.x, w = tid >> 5, lane = tid & 31;
    int g = lane >> 2, tq = lane & 3;
    int e0 = blockIdx.x * 128;
    int m0 = e0 + w*16;

    uint32_t af[4][4];
    load_a_f16(g_ea16, m0, g, tq, af);
    {
        const uint4* sw = (const uint4*)w1;
        #pragma unroll
        for(int i = 0; i < 4; i++){
            int idx = i*256 + tid;
            int f = idx >> 3, u = idx & 7;
            *(uint4*)&Bs[f*BPAD + u*8] = sw[idx];
        }
    }
    __syncthreads();

    float acc[16][4];
    #pragma unroll
    for(int j = 0; j < 16; j++)
        #pragma unroll
        for(int i = 0; i < 4; i++) acc[j][i] = 0.f;

    #pragma unroll
    for(int ks = 0; ks < 4; ks++){
        int cb0 = ks*16 + 2*tq, cb1 = cb0 + 8;
        #pragma unroll
        for(int j = 0; j < 16; j++){
            int row = (j*8 + g)*BPAD;
            uint32_t b0 = *(const uint32_t*)&Bs[row + cb0];
            uint32_t b1 = *(const uint32_t*)&Bs[row + cb1];
            mma_f16(acc[j], af[ks], b0, b1);
        }
    }

    __half* a0 = g_a16 + (size_t)(m0 + g)*128;
    __half* a1 = g_a16 + (size_t)(m0 + g + 8)*128;
    #pragma unroll
    for(int j = 0; j < 16; j++){
        int c = j*8 + 2*tq;
        float2 bb = *(const float2*)&b1l[c];
        *(__half2*)&a0[c] = __floats2half2_rn(leaky(acc[j][0] + bb.x), leaky(acc[j][1] + bb.y));
        *(__half2*)&a1[c] = __floats2half2_rn(leaky(acc[j][2] + bb.x), leaky(acc[j][3] + bb.y));
    }
}

// ---------------- Q via mma v5 (monolithic, unchanged from R15) ----------------------
#define DPAD 72
__global__ __launch_bounds__(256, 2) void k_q_mma(int layer){
    __shared__ __align__(16) char smem_raw[18432];
    __half* Bh = (__half*)smem_raw;
    __half* Ds = (__half*)smem_raw;
    const __half* w2 = g_w2t + (size_t)layer*Hh*4096;
    int tid = threadIdx.x, w = tid >> 5, lane = tid & 31;
    int g = lane >> 2, tq = lane & 3;
    int n0 = blockIdx.x * 256;
    int m0 = n0 + w*32;

    uint32_t a0f[4][4], a1f[4][4];
    load_a_f16(g_h16, m0,      g, tq, a0f);
    load_a_f16(g_h16, m0 + 16, g, tq, a1f);

    int sel = lane >> 3, rw = lane & 7;
    uint32_t lds_base = (uint32_t)__cvta_generic_to_shared(
        &Bh[rw*BPAD + (sel & 1)*8 + (sel >> 1)*16]);

    int kbase = blockIdx.y*8;
    uint4 pf0, pf1;
    {
        const uint4* sw = (const uint4*)(w2 + (size_t)kbase*4096);
        pf0 = sw[tid]; pf1 = sw[256 + tid];
    }
    int f0 = tid >> 3,         u0 = tid & 7;
    int f1 = (256 + tid) >> 3, u1 = tid & 7;

    __half* ds = Ds + w*16*DPAD;

    for(int kk = 0; kk < 8; kk++){
        int k = kbase + kk;
        __syncthreads();
        *(uint4*)&Bh[f0*BPAD + u0*8] = pf0;
        *(uint4*)&Bh[f1*BPAD + u1*8] = pf1;
        if(kk < 7){
            const uint4* sw = (const uint4*)(w2 + (size_t)(k + 1)*4096);
            pf0 = sw[tid]; pf1 = sw[256 + tid];
        }
        __syncthreads();

        float acc0[8][4], acc1[8][4];
        #pragma unroll
        for(int j = 0; j < 8; j++)
            #pragma unroll
            for(int i = 0; i < 4; i++){ acc0[j][i] = 0.f; acc1[j][i] = 0.f; }

        #pragma unroll
        for(int ksp = 0; ksp < 2; ksp++){
            #pragma unroll
            for(int j = 0; j < 8; j++){
                uint32_t b00, b01, b10, b11;
                ldsm_x4(b00, b01, b10, b11,
                        lds_base + (uint32_t)((j*8*BPAD + ksp*32)*2));
                mma_f16(acc0[j], a0f[2*ksp],     b00, b01);
                mma_f16(acc0[j], a0f[2*ksp + 1], b10, b11);
                mma_f16(acc1[j], a1f[2*ksp],     b00, b01);
                mma_f16(acc1[j], a1f[2*ksp + 1], b10, b11);
            }
        }
        __syncthreads();

        #pragma unroll
        for(int j = 0; j < 8; j++){
            int c = j*8 + 2*tq;
            *(__half2*)&ds[g*DPAD + c]       = __floats2half2_rn(acc0[j][0], acc0[j][1]);
            *(__half2*)&ds[(g + 8)*DPAD + c] = __floats2half2_rn(acc0[j][2], acc0[j][3]);
        }
        __syncwarp();
        #pragma unroll
        for(int i = 0; i < 4; i++){
            int idx = i*32 + lane;
            int r = idx >> 3, u = idx & 7;
            uint4 v = *(const uint4*)&ds[r*DPAD + u*8];
            *(uint4*)(g_Q + ((size_t)(m0 + r)*128 + k)*64 + u*8) = v;
        }
        __syncwarp();
        #pragma unroll
        for(int j = 0; j < 8; j++){
            int c = j*8 + 2*tq;
            *(__half2*)&ds[g*DPAD + c]       = __floats2half2_rn(acc1[j][0], acc1[j][1]);
            *(__half2*)&ds[(g + 8)*DPAD + c] = __floats2half2_rn(acc1[j][2], acc1[j][3]);
        }
        __syncwarp();
        #pragma unroll
        for(int i = 0; i < 4; i++){
            int idx = i*32 + lane;
            int r = idx >> 3, u = idx & 7;
            uint4 v = *(const uint4*)&ds[r*DPAD + u*8];
            *(uint4*)(g_Q + ((size_t)(m0 + 16 + r)*128 + k)*64 + u*8) = v;
        }
    }
}

// ---------------- messages v5: tensor-core (edges = M), 1 warp per node --------------
// msg[e,f] = sum_k a16[e,k] * Q[n,k,f] + y2[n,f]; up to 16 edges per mma batch.
// B frags via ldmatrix.x4.trans on Qs[k][f] (pitch 72): lane groups map to tiles
// (k0-7,f0),(k8-15,f0),(k0-7,f0+8),(k8-15,f0+8) -> (b0,b1) of two f-tiles.
#define QPITCH 72
__global__ __launch_bounds__(64) void k_msg2(){
    __shared__ __align__(16) __half Qs[2*128*QPITCH];   // 36864 B
    __shared__ float y2s[2][64];
    int w = threadIdx.x >> 5, lane = threadIdx.x & 31;
    int n = blockIdx.x*2 + w;
    int beg = g_rowptr[n], end = g_rowptr[n+1];
    __half* qs = Qs + w*128*QPITCH;
    int g = lane >> 2, tq = lane & 3;

    if(beg < end){
        const uint4* src = (const uint4*)(g_Q + (size_t)n*8192);
        #pragma unroll
        for(int i = 0; i < 32; i++){
            int idx = i*32 + lane;
            int k = idx >> 3, u = idx & 7;
            *(uint4*)&qs[k*QPITCH + u*8] = src[idx];
        }
        y2s[w][lane]      = g_y2[n*64 + lane];
        y2s[w][32 + lane] = g_y2[n*64 + 32 + lane];
    }
    __syncwarp();
    if(beg >= end) return;

    int lrow = ((lane >> 3) & 1)*8 + (lane & 7);   // k row within 16-window
    int lcol = (lane >> 4)*8;                       // f offset 0 or 8
    uint32_t lds_base = (uint32_t)__cvta_generic_to_shared(&qs[lrow*QPITCH + lcol]);

    float2 y2v[8];
    #pragma unroll
    for(int j = 0; j < 8; j++) y2v[j] = *(const float2*)&y2s[w][j*8 + 2*tq];

    for(int base = beg; base < end; base += 16){
        int i0 = base + g, i1 = base + g + 8;
        bool v0 = i0 < end, v1 = i1 < end;
        int e0 = v0 ? g_eidx[i0] : 0;
        int e1 = v1 ? g_eidx[i1] : 0;
        int d0 = v0 ? g_edst[i0] : 0;
        int d1 = v1 ? g_edst[i1] : 0;
        const __half* p0 = g_a16 + (size_t)e0*128;
        const __half* p1 = g_a16 + (size_t)e1*128;

        float c[8][4];
        #pragma unroll
        for(int j = 0; j < 8; j++)
            #pragma unroll
            for(int i = 0; i < 4; i++) c[j][i] = 0.f;

        #pragma unroll
        for(int kt = 0; kt < 8; kt++){
            uint32_t a[4];
            int c0 = kt*16 + 2*tq;
            a[0] = v0 ? *(const uint32_t*)&p0[c0]     : 0u;
            a[1] = v1 ? *(const uint32_t*)&p1[c0]     : 0u;
            a[2] = v0 ? *(const uint32_t*)&p0[c0 + 8] : 0u;
            a[3] = v1 ? *(const uint32_t*)&p1[c0 + 8] : 0u;
            #pragma unroll
            for(int ft2 = 0; ft2 < 4; ft2++){
                uint32_t b0, b1, b2, b3;
                ldsm_x4_t(b0, b1, b2, b3,
                          lds_base + (uint32_t)((kt*16*QPITCH + ft2*16)*2));
                mma_f16(c[2*ft2],     a, b0, b1);
                mma_f16(c[2*ft2 + 1], a, b2, b3);
            }
        }

        #pragma unroll
        for(int j = 0; j < 8; j++){
            int f = j*8 + 2*tq;
            if(v0){
                atomicAdd(&g_num[d0*64 + f],     c[j][0] + y2v[j].x);
                atomicAdd(&g_num[d0*64 + f + 1], c[j][1] + y2v[j].y);
            }
            if(v1){
                atomicAdd(&g_num[d1*64 + f],     c[j][2] + y2v[j].x);
                atomicAdd(&g_num[d1*64 + f + 1], c[j][3] + y2v[j].y);
            }
        }
    }
}

// ---------------- shared 64x64 small GEMM with three epilogues -----------------------
__global__ __launch_bounds__(256) void k_nn64(const float* __restrict__ B,
                                              const float* __restrict__ bias,
                                              const float* __restrict__ cb,
                                              const int* __restrict__ batch,
                                              int mode){
    __shared__ float As[64][64];
    __shared__ float Bs[64][64];
    const float* A = (mode == 2) ? g_x : g_h;
    int tid = threadIdx.x;
    int n0 = blockIdx.x * 64;
    #pragma unroll
    for(int i = 0; i < 4; i++){
        int idx = i*256 + tid; int m = idx >> 4, d = (idx & 15) * 4;
        *(float4*)&As[m][d] = *(const float4*)&A[(size_t)(n0 + m)*64 + d];
        *(float4*)&Bs[m][d] = *(const float4*)&B[(size_t)m*64 + d];
    }
    __syncthreads();
    int tx = tid & 15, ty = tid >> 4;
    float acc[4][4];
    #pragma unroll
    for(int i = 0; i < 4; i++)
        #pragma unroll
        for(int j = 0; j < 4; j++) acc[i][j] = 0.f;

    #pragma unroll 4
    for(int d4 = 0; d4 < 64; d4 += 4){
        float4 a[4];
        #pragma unroll
        for(int i = 0; i < 4; i++) a[i] = *(float4*)&As[ty*4 + i][d4];
        #pragma unroll
        for(int dd = 0; dd < 4; dd++){
            float4 bv = *(float4*)&Bs[d4 + dd][tx*4];
            #pragma unroll
            for(int i = 0; i < 4; i++){
                float av = (dd==0)?a[i].x:(dd==1)?a[i].y:(dd==2)?a[i].z:a[i].w;
                acc[i][0] = fmaf(av, bv.x, acc[i][0]);
                acc[i][1] = fmaf(av, bv.y, acc[i][1]);
                acc[i][2] = fmaf(av, bv.z, acc[i][2]);
                acc[i][3] = fmaf(av, bv.w, acc[i][3]);
            }
        }
    }
    if(mode == 0){
        #pragma unroll
        for(int i = 0; i < 4; i++){
            float4 o; o.x = acc[i][0]; o.y = acc[i][1]; o.z = acc[i][2]; o.w = acc[i][3];
            *(float4*)&g_y2[(size_t)(n0 + ty*4 + i)*64 + tx*4] = o;
        }
    } else if(mode == 1){
        #pragma unroll
        for(int i = 0; i < 4; i++){
            int n = n0 + ty*4 + i;
            float inv = 1.f / fmaxf(g_deg[n], 1.f);
            #pragma unroll
            for(int j = 0; j < 4; j++){
                int idx = n*64 + tx*4 + j;
                float v = g_x[idx] + g_num[idx]*inv + acc[i][j] + cb[tx*4 + j];
                g_x[idx] = v;
                g_num[idx] = 0.f;
            }
        }
    } else {
        #pragma unroll
        for(int i = 0; i < 4; i++){
            int n = n0 + ty*4 + i;
            int b = batch[n];
            #pragma unroll
            for(int j = 0; j < 4; j++)
                atomicAdd(&g_pool[b*64 + tx*4 + j], acc[i][j] + bias[tx*4 + j]);
        }
    }
}

// ---------------- head ----------------------------------------------------------------
__global__ void k_out(const float* __restrict__ oW, const float* __restrict__ ob,
                      float* __restrict__ out){
    __shared__ float p[64];
    int g = blockIdx.x, t = threadIdx.x;
    if(t < 64){
        float c = fmaxf(g_cnt[g], 1.f);
        p[t] = leaky(g_pool[g*64 + t] / c);
    }
    __syncthreads();
    float acc = ob[t];
    #pragma unroll 8
    for(int f = 0; f < 64; f++)
        acc = fmaf(p[f], oW[f*128 + t], acc);
    out[g*128 + t] = acc;
}

// ---------------- launch ----------------------------------------------------------------
extern "C" void kernel_launch(void* const* d_in, const int* in_sizes, int n_in,
                              void* d_out, int out_size){
    const float* x    = (const float*)d_in[0];
    const int*   ei   = (const int*)  d_in[1];
    const float* ea   = (const float*)d_in[2];
    const int*   batch= (const int*)  d_in[3];
    const float* lns  = (const float*)d_in[4];
    const float* lnb  = (const float*)d_in[5];
    const float* W1   = (const float*)d_in[6];
    const float* b1   = (const float*)d_in[7];
    const float* W2   = (const float*)d_in[8];
    const float* b2   = (const float*)d_in[9];
    const float* root = (const float*)d_in[10];
    const float* cb   = (const float*)d_in[11];
    const float* dW   = (const float*)d_in[12];
    const float* db   = (const float*)d_in[13];
    const float* oW   = (const float*)d_in[14];
    const float* ob   = (const float*)d_in[15];
    float* out = (float*)d_out;

    dim3 gq(Nn/256, Hh/8);

    // Launch index 3 (ncu capture slot) = k_q_mma(layer 0).
    k_prep<<<(Ne*Dd + 255)/256, 256>>>(W2, W1, ea);            // 0
    k_init<<<(Nn*Dd + 255)/256, 256>>>(x);                     // 1
    k_ln<<<Nn/8, 256>>>(lns, lnb);                             // 2
    k_q_mma<<<gq, 256>>>(0);                                   // 3  <- profiled
    k_degcnt<<<(Ne + 255)/256, 256>>>(ei, batch);              // 4
    k_scan<<<1, 1024>>>();                                     // 5
    k_fill<<<(Ne + 255)/256, 256>>>(ei);                       // 6
    k_emlp_mma<<<Ne/128, 256>>>(0, b1);                        // 7
    k_nn64<<<Nn/64, 256>>>(b2, nullptr, nullptr, nullptr, 0);  // 8: y2 = h@B2
    k_msg2<<<Nn/2, 64>>>();                                    // 9
    k_nn64<<<Nn/64, 256>>>(root, nullptr, cb, nullptr, 1);     // 10

    for(int l = 1; l < Ll; l++){
        k_ln<<<Nn/8, 256>>>(lns + l*64, lnb + l*64);
        k_emlp_mma<<<Ne/128, 256>>>(l, b1 + (size_t)l*128);
        k_nn64<<<Nn/64, 256>>>(b2 + (size_t)l*4096, nullptr, nullptr, nullptr, 0);
        k_q_mma<<<gq, 256>>>(l);
        k_msg2<<<Nn/2, 64>>>();
        k_nn64<<<Nn/64, 256>>>(root + (size_t)l*4096, nullptr, cb + (size_t)l*64, nullptr, 1);
    }

    k_nn64<<<Nn/64, 256>>>(dW, db, nullptr, batch, 2);  // dense + pool
    k_out<<<Gg, 128>>>(oW, ob, out);
}

// round 17
// speedup vs baseline: 1.2180x; 1.0277x over previous
#include <cuda_runtime.h>
#include <cuda_bf16.h>
#include <cuda_fp16.h>
#include <cstdint>

#define Nn 16384
#define Ne 65536
#define Dd 64
#define Hh 128
#define Ll 3
#define Gg 512
#define Oo 128

// ---------------- scratch -------------------------------------------------------
__device__ float g_x[Nn*Dd];
__device__ float g_h[Nn*Dd];
__device__ __half g_h16[Nn*Dd];
__device__ float g_y2[Nn*Dd];
__device__ __half g_a16[(size_t)Ne*Hh];                  // edge MLP out, fp16
__device__ __half g_Q[(size_t)Nn*Hh*Dd];                 // [n][k][f], fp16, 256 MB
__device__ __half g_w2t[(size_t)Ll*Hh*Dd*Dd];           // [l][k][f][d] fp16
__device__ __half g_w1t[(size_t)Ll*Hh*Dd];              // [l][f=128][d=64] fp16
__device__ __half g_ea16[(size_t)Ne*Dd];
__device__ float g_num[Nn*Dd];
__device__ float g_deg[Nn];
__device__ float g_pool[Gg*Dd];
__device__ float g_cnt[Gg];
// CSR by src
__device__ int g_srccnt[Nn];
__device__ int g_cursor[Nn];
__device__ int g_rowptr[Nn + 1];
__device__ int g_edst[Ne];
__device__ int g_eidx[Ne];

__device__ __forceinline__ float leaky(float v){ return v > 0.f ? v : 0.01f*v; }

// ---------------- merged weight/edge prep ------------------------------------------
__global__ void k_prep(const float* __restrict__ W2, const float* __restrict__ W1,
                       const float* __restrict__ ea){
    int idx = blockIdx.x*blockDim.x + threadIdx.x;
    if(idx < Ne*Dd){
        g_ea16[idx] = __float2half(ea[idx]);
    }
    if(idx < Ll*Hh*Dd*Dd){
        int lk = idx >> 12;
        int d = (idx >> 6) & 63;
        int f = idx & 63;
        g_w2t[(size_t)lk*4096 + f*64 + d] = __float2half(W2[idx]);
    }
    if(idx < Ll*Dd*Hh){
        int l = idx >> 13;
        int d = (idx >> 7) & 63;
        int f = idx & 127;
        g_w1t[(size_t)l*Hh*Dd + f*64 + d] = __float2half(W1[idx]);
    }
}

// ---------------- init --------------------------------------------------------------
__global__ void k_init(const float* __restrict__ x){
    int i = blockIdx.x*blockDim.x + threadIdx.x;
    if(i < Nn*Dd){ g_x[i] = x[i]; g_num[i] = 0.f; }
    if(i < Gg*Dd) g_pool[i] = 0.f;
    if(i < Nn){ g_deg[i] = 0.f; g_srccnt[i] = 0; g_cursor[i] = 0; }
    if(i < Gg)  g_cnt[i] = 0.f;
}

__global__ void k_degcnt(const int* __restrict__ ei, const int* __restrict__ batch){
    int i = blockIdx.x*blockDim.x + threadIdx.x;
    if(i < Ne){
        atomicAdd(&g_deg[ei[Ne + i]], 1.f);
        atomicAdd(&g_srccnt[ei[i]], 1);
    }
    if(i < Nn) atomicAdd(&g_cnt[batch[i]], 1.f);
}

// single-block exclusive scan of g_srccnt -> g_rowptr
__global__ void k_scan(){
    __shared__ int wsum[32];
    int t = threadIdx.x;
    int base = t*16;
    int c[16]; int s = 0;
    #pragma unroll
    for(int i = 0; i < 16; i++){ c[i] = g_srccnt[base + i]; s += c[i]; }
    int lane = t & 31, w = t >> 5;
    int v = s;
    #pragma unroll
    for(int o = 1; o < 32; o <<= 1){ int u = __shfl_up_sync(~0u, v, o); if(lane >= o) v += u; }
    if(lane == 31) wsum[w] = v;
    __syncthreads();
    if(w == 0){
        int x = wsum[lane];
        #pragma unroll
        for(int o = 1; o < 32; o <<= 1){ int u = __shfl_up_sync(~0u, x, o); if(lane >= o) x += u; }
        wsum[lane] = x;
    }
    __syncthreads();
    int run = v - s + (w > 0 ? wsum[w-1] : 0);
    #pragma unroll
    for(int i = 0; i < 16; i++){ g_rowptr[base + i] = run; run += c[i]; }
    if(t == 1023) g_rowptr[Nn] = run;
}

__global__ void k_fill(const int* __restrict__ ei){
    int e = blockIdx.x*blockDim.x + threadIdx.x;
    if(e >= Ne) return;
    int src = ei[e];
    int pos = g_rowptr[src] + atomicAdd(&g_cursor[src], 1);
    g_edst[pos] = ei[Ne + e];
    g_eidx[pos] = e;
}

// ---------------- h = leaky(LN(x)); also emit fp16 ----------------------------------
__global__ void k_ln(const float* __restrict__ sc, const float* __restrict__ bi){
    int lane = threadIdx.x & 31, w = threadIdx.x >> 5;
    int n = blockIdx.x*8 + w;
    float v0 = g_x[n*64 + lane], v1 = g_x[n*64 + 32 + lane];
    float s = v0 + v1;
    #pragma unroll
    for(int o = 16; o; o >>= 1) s += __shfl_xor_sync(0xffffffffu, s, o);
    float mu = s * 0.015625f;
    float d0 = v0 - mu, d1 = v1 - mu;
    float q = d0*d0 + d1*d1;
    #pragma unroll
    for(int o = 16; o; o >>= 1) q += __shfl_xor_sync(0xffffffffu, q, o);
    float r = rsqrtf(q * 0.015625f + 1e-5f);
    float h0 = leaky(d0*r*sc[lane]      + bi[lane]);
    float h1 = leaky(d1*r*sc[32 + lane] + bi[32 + lane]);
    g_h[n*64 + lane]      = h0;
    g_h[n*64 + 32 + lane] = h1;
    g_h16[n*64 + lane]      = __float2half(h0);
    g_h16[n*64 + 32 + lane] = __float2half(h1);
}

// ---------------- mma helpers --------------------------------------------------------
#define BPAD 72
__device__ __forceinline__ void mma_f16(float* c, const uint32_t* a, uint32_t b0, uint32_t b1){
    asm volatile(
        "mma.sync.aligned.m16n8k16.row.col.f32.f16.f16.f32 "
        "{%0,%1,%2,%3}, {%4,%5,%6,%7}, {%8,%9}, {%0,%1,%2,%3};"
        : "+f"(c[0]), "+f"(c[1]), "+f"(c[2]), "+f"(c[3])
        : "r"(a[0]), "r"(a[1]), "r"(a[2]), "r"(a[3]), "r"(b0), "r"(b1));
}
__device__ __forceinline__ void ldsm_x4(uint32_t& r0, uint32_t& r1, uint32_t& r2, uint32_t& r3,
                                        uint32_t addr){
    asm volatile("ldmatrix.sync.aligned.m8n8.x4.shared.b16 {%0,%1,%2,%3}, [%4];"
        : "=r"(r0), "=r"(r1), "=r"(r2), "=r"(r3) : "r"(addr));
}
__device__ __forceinline__ void ldsm_x4_t(uint32_t& r0, uint32_t& r1, uint32_t& r2, uint32_t& r3,
                                          uint32_t addr){
    asm volatile("ldmatrix.sync.aligned.m8n8.x4.trans.shared.b16 {%0,%1,%2,%3}, [%4];"
        : "=r"(r0), "=r"(r1), "=r"(r2), "=r"(r3) : "r"(addr));
}

__device__ __forceinline__ void load_a_f16(const __half* p, int m0, int g, int tq,
                                           uint32_t a[4][4]){
    int r0 = (m0 + g)*64, r1 = (m0 + g + 8)*64;
    #pragma unroll
    for(int ks = 0; ks < 4; ks++){
        int c0 = ks*16 + 2*tq, c1 = c0 + 8;
        a[ks][0] = *(const uint32_t*)&p[r0 + c0];
        a[ks][1] = *(const uint32_t*)&p[r1 + c0];
        a[ks][2] = *(const uint32_t*)&p[r0 + c1];
        a[ks][3] = *(const uint32_t*)&p[r1 + c1];
    }
}

// ---------------- a = leaky(ea @ W1 + b1), pure fp16; OUTPUT fp16 --------------------
__global__ __launch_bounds__(256) void k_emlp_mma(int layer, const float* __restrict__ b1l){
    __shared__ __align__(16) __half Bs[128*BPAD];
    const __half* w1 = g_w1t + (size_t)layer*Hh*Dd;
    int tid = threadIdx.x, w = tid >> 5, lane = tid & 31;
    int g = lane >> 2, tq = lane & 3;
    int e0 = blockIdx.x * 128;
    int m0 = e0 + w*16;

    uint32_t af[4][4];
    load_a_f16(g_ea16, m0, g, tq, af);
    {
        const uint4* sw = (const uint4*)w1;
        #pragma unroll
        for(int i = 0; i < 4; i++){
            int idx = i*256 + tid;
            int f = idx >> 3, u = idx & 7;
            *(uint4*)&Bs[f*BPAD + u*8] = sw[idx];
        }
    }
    __syncthreads();

    float acc[16][4];
    #pragma unroll
    for(int j = 0; j < 16; j++)
        #pragma unroll
        for(int i = 0; i < 4; i++) acc[j][i] = 0.f;

    #pragma unroll
    for(int ks = 0; ks < 4; ks++){
        int cb0 = ks*16 + 2*tq, cb1 = cb0 + 8;
        #pragma unroll
        for(int j = 0; j < 16; j++){
            int row = (j*8 + g)*BPAD;
            uint32_t b0 = *(const uint32_t*)&Bs[row + cb0];
            uint32_t b1 = *(const uint32_t*)&Bs[row + cb1];
            mma_f16(acc[j], af[ks], b0, b1);
        }
    }

    __half* a0 = g_a16 + (size_t)(m0 + g)*128;
    __half* a1 = g_a16 + (size_t)(m0 + g + 8)*128;
    #pragma unroll
    for(int j = 0; j < 16; j++){
        int c = j*8 + 2*tq;
        float2 bb = *(const float2*)&b1l[c];
        *(__half2*)&a0[c] = __floats2half2_rn(leaky(acc[j][0] + bb.x), leaky(acc[j][1] + bb.y));
        *(__half2*)&a1[c] = __floats2half2_rn(leaky(acc[j][2] + bb.x), leaky(acc[j][3] + bb.y));
    }
}

// ---------------- Q via mma v6: 128-thread CTAs, 4 CTAs/SM ---------------------------
// Same per-warp tiling as v5 (32 rows/warp, 1-term fp16), but 4-warp CTAs:
// cheaper barriers, 4 independent CTAs/SM so epilogue of one overlaps mma of another.
// B (9216B) unions with Ds (4 warps x 16 x DPAD = 9216B).
#define DPAD 72
__global__ __launch_bounds__(128, 4) void k_q_mma(int layer){
    __shared__ __align__(16) char smem_raw[9216];
    __half* Bh = (__half*)smem_raw;
    __half* Ds = (__half*)smem_raw;
    const __half* w2 = g_w2t + (size_t)layer*Hh*4096;
    int tid = threadIdx.x, w = tid >> 5, lane = tid & 31;
    int g = lane >> 2, tq = lane & 3;
    int n0 = blockIdx.x * 128;
    int m0 = n0 + w*32;

    uint32_t a0f[4][4], a1f[4][4];
    load_a_f16(g_h16, m0,      g, tq, a0f);
    load_a_f16(g_h16, m0 + 16, g, tq, a1f);

    int sel = lane >> 3, rw = lane & 7;
    uint32_t lds_base = (uint32_t)__cvta_generic_to_shared(
        &Bh[rw*BPAD + (sel & 1)*8 + (sel >> 1)*16]);

    int kbase = blockIdx.y*8;
    uint4 pf[4];
    {
        const uint4* sw = (const uint4*)(w2 + (size_t)kbase*4096);
        #pragma unroll
        for(int i = 0; i < 4; i++) pf[i] = sw[i*128 + tid];
    }
    int fb = tid >> 3, ub = tid & 7;   // f = i*16 + fb

    __half* ds = Ds + w*16*DPAD;

    for(int kk = 0; kk < 8; kk++){
        int k = kbase + kk;
        __syncthreads();                       // prev D staging complete
        #pragma unroll
        for(int i = 0; i < 4; i++)
            *(uint4*)&Bh[(i*16 + fb)*BPAD + ub*8] = pf[i];
        if(kk < 7){
            const uint4* sw = (const uint4*)(w2 + (size_t)(k + 1)*4096);
            #pragma unroll
            for(int i = 0; i < 4; i++) pf[i] = sw[i*128 + tid];
        }
        __syncthreads();                       // B visible

        float acc0[8][4], acc1[8][4];
        #pragma unroll
        for(int j = 0; j < 8; j++)
            #pragma unroll
            for(int i = 0; i < 4; i++){ acc0[j][i] = 0.f; acc1[j][i] = 0.f; }

        #pragma unroll
        for(int ksp = 0; ksp < 2; ksp++){
            #pragma unroll
            for(int j = 0; j < 8; j++){
                uint32_t b00, b01, b10, b11;
                ldsm_x4(b00, b01, b10, b11,
                        lds_base + (uint32_t)((j*8*BPAD + ksp*32)*2));
                mma_f16(acc0[j], a0f[2*ksp],     b00, b01);
                mma_f16(acc0[j], a0f[2*ksp + 1], b10, b11);
                mma_f16(acc1[j], a1f[2*ksp],     b00, b01);
                mma_f16(acc1[j], a1f[2*ksp + 1], b10, b11);
            }
        }
        __syncthreads();                       // all warps done reading B

        // m-half 0: stage + coalesced store (rows m0..m0+15)
        #pragma unroll
        for(int j = 0; j < 8; j++){
            int c = j*8 + 2*tq;
            *(__half2*)&ds[g*DPAD + c]       = __floats2half2_rn(acc0[j][0], acc0[j][1]);
            *(__half2*)&ds[(g + 8)*DPAD + c] = __floats2half2_rn(acc0[j][2], acc0[j][3]);
        }
        __syncwarp();
        #pragma unroll
        for(int i = 0; i < 4; i++){
            int idx = i*32 + lane;
            int r = idx >> 3, u = idx & 7;
            uint4 v = *(const uint4*)&ds[r*DPAD + u*8];
            *(uint4*)(g_Q + ((size_t)(m0 + r)*128 + k)*64 + u*8) = v;
        }
        __syncwarp();
        // m-half 1
        #pragma unroll
        for(int j = 0; j < 8; j++){
            int c = j*8 + 2*tq;
            *(__half2*)&ds[g*DPAD + c]       = __floats2half2_rn(acc1[j][0], acc1[j][1]);
            *(__half2*)&ds[(g + 8)*DPAD + c] = __floats2half2_rn(acc1[j][2], acc1[j][3]);
        }
        __syncwarp();
        #pragma unroll
        for(int i = 0; i < 4; i++){
            int idx = i*32 + lane;
            int r = idx >> 3, u = idx & 7;
            uint4 v = *(const uint4*)&ds[r*DPAD + u*8];
            *(uint4*)(g_Q + ((size_t)(m0 + 16 + r)*128 + k)*64 + u*8) = v;
        }
    }
}

// ---------------- messages v5: tensor-core (edges = M), 1 warp per node --------------
#define QPITCH 72
__global__ __launch_bounds__(64) void k_msg2(){
    __shared__ __align__(16) __half Qs[2*128*QPITCH];   // 36864 B
    __shared__ float y2s[2][64];
    int w = threadIdx.x >> 5, lane = threadIdx.x & 31;
    int n = blockIdx.x*2 + w;
    int beg = g_rowptr[n], end = g_rowptr[n+1];
    __half* qs = Qs + w*128*QPITCH;
    int g = lane >> 2, tq = lane & 3;

    if(beg < end){
        const uint4* src = (const uint4*)(g_Q + (size_t)n*8192);
        #pragma unroll
        for(int i = 0; i < 32; i++){
            int idx = i*32 + lane;
            int k = idx >> 3, u = idx & 7;
            *(uint4*)&qs[k*QPITCH + u*8] = src[idx];
        }
        y2s[w][lane]      = g_y2[n*64 + lane];
        y2s[w][32 + lane] = g_y2[n*64 + 32 + lane];
    }
    __syncwarp();
    if(beg >= end) return;

    int lrow = ((lane >> 3) & 1)*8 + (lane & 7);
    int lcol = (lane >> 4)*8;
    uint32_t lds_base = (uint32_t)__cvta_generic_to_shared(&qs[lrow*QPITCH + lcol]);

    float2 y2v[8];
    #pragma unroll
    for(int j = 0; j < 8; j++) y2v[j] = *(const float2*)&y2s[w][j*8 + 2*tq];

    for(int base = beg; base < end; base += 16){
        int i0 = base + g, i1 = base + g + 8;
        bool v0 = i0 < end, v1 = i1 < end;
        int e0 = v0 ? g_eidx[i0] : 0;
        int e1 = v1 ? g_eidx[i1] : 0;
        int d0 = v0 ? g_edst[i0] : 0;
        int d1 = v1 ? g_edst[i1] : 0;
        const __half* p0 = g_a16 + (size_t)e0*128;
        const __half* p1 = g_a16 + (size_t)e1*128;

        float c[8][4];
        #pragma unroll
        for(int j = 0; j < 8; j++)
            #pragma unroll
            for(int i = 0; i < 4; i++) c[j][i] = 0.f;

        #pragma unroll
        for(int kt = 0; kt < 8; kt++){
            uint32_t a[4];
            int c0 = kt*16 + 2*tq;
            a[0] = v0 ? *(const uint32_t*)&p0[c0]     : 0u;
            a[1] = v1 ? *(const uint32_t*)&p1[c0]     : 0u;
            a[2] = v0 ? *(const uint32_t*)&p0[c0 + 8] : 0u;
            a[3] = v1 ? *(const uint32_t*)&p1[c0 + 8] : 0u;
            #pragma unroll
            for(int ft2 = 0; ft2 < 4; ft2++){
                uint32_t b0, b1, b2, b3;
                ldsm_x4_t(b0, b1, b2, b3,
                          lds_base + (uint32_t)((kt*16*QPITCH + ft2*16)*2));
                mma_f16(c[2*ft2],     a, b0, b1);
                mma_f16(c[2*ft2 + 1], a, b2, b3);
            }
        }

        #pragma unroll
        for(int j = 0; j < 8; j++){
            int f = j*8 + 2*tq;
            if(v0){
                atomicAdd(&g_num[d0*64 + f],     c[j][0] + y2v[j].x);
                atomicAdd(&g_num[d0*64 + f + 1], c[j][1] + y2v[j].y);
            }
            if(v1){
                atomicAdd(&g_num[d1*64 + f],     c[j][2] + y2v[j].x);
                atomicAdd(&g_num[d1*64 + f + 1], c[j][3] + y2v[j].y);
            }
        }
    }
}

// ---------------- shared 64x64 small GEMM with three epilogues -----------------------
__global__ __launch_bounds__(256) void k_nn64(const float* __restrict__ B,
                                              const float* __restrict__ bias,
                                              const float* __restrict__ cb,
                                              const int* __restrict__ batch,
                                              int mode){
    __shared__ float As[64][64];
    __shared__ float Bs[64][64];
    const float* A = (mode == 2) ? g_x : g_h;
    int tid = threadIdx.x;
    int n0 = blockIdx.x * 64;
    #pragma unroll
    for(int i = 0; i < 4; i++){
        int idx = i*256 + tid; int m = idx >> 4, d = (idx & 15) * 4;
        *(float4*)&As[m][d] = *(const float4*)&A[(size_t)(n0 + m)*64 + d];
        *(float4*)&Bs[m][d] = *(const float4*)&B[(size_t)m*64 + d];
    }
    __syncthreads();
    int tx = tid & 15, ty = tid >> 4;
    float acc[4][4];
    #pragma unroll
    for(int i = 0; i < 4; i++)
        #pragma unroll
        for(int j = 0; j < 4; j++) acc[i][j] = 0.f;

    #pragma unroll 4
    for(int d4 = 0; d4 < 64; d4 += 4){
        float4 a[4];
        #pragma unroll
        for(int i = 0; i < 4; i++) a[i] = *(float4*)&As[ty*4 + i][d4];
        #pragma unroll
        for(int dd = 0; dd < 4; dd++){
            float4 bv = *(float4*)&Bs[d4 + dd][tx*4];
            #pragma unroll
            for(int i = 0; i < 4; i++){
                float av = (dd==0)?a[i].x:(dd==1)?a[i].y:(dd==2)?a[i].z:a[i].w;
                acc[i][0] = fmaf(av, bv.x, acc[i][0]);
                acc[i][1] = fmaf(av, bv.y, acc[i][1]);
                acc[i][2] = fmaf(av, bv.z, acc[i][2]);
                acc[i][3] = fmaf(av, bv.w, acc[i][3]);
            }
        }
    }
    if(mode == 0){
        #pragma unroll
        for(int i = 0; i < 4; i++){
            float4 o; o.x = acc[i][0]; o.y = acc[i][1]; o.z = acc[i][2]; o.w = acc[i][3];
            *(float4*)&g_y2[(size_t)(n0 + ty*4 + i)*64 + tx*4] = o;
        }
    } else if(mode == 1){
        #pragma unroll
        for(int i = 0; i < 4; i++){
            int n = n0 + ty*4 + i;
            float inv = 1.f / fmaxf(g_deg[n], 1.f);
            #pragma unroll
            for(int j = 0; j < 4; j++){
                int idx = n*64 + tx*4 + j;
                float v = g_x[idx] + g_num[idx]*inv + acc[i][j] + cb[tx*4 + j];
                g_x[idx] = v;
                g_num[idx] = 0.f;
            }
        }
    } else {
        #pragma unroll
        for(int i = 0; i < 4; i++){
            int n = n0 + ty*4 + i;
            int b = batch[n];
            #pragma unroll
            for(int j = 0; j < 4; j++)
                atomicAdd(&g_pool[b*64 + tx*4 + j], acc[i][j] + bias[tx*4 + j]);
        }
    }
}

// ---------------- head ----------------------------------------------------------------
__global__ void k_out(const float* __restrict__ oW, const float* __restrict__ ob,
                      float* __restrict__ out){
    __shared__ float p[64];
    int g = blockIdx.x, t = threadIdx.x;
    if(t < 64){
        float c = fmaxf(g_cnt[g], 1.f);
        p[t] = leaky(g_pool[g*64 + t] / c);
    }
    __syncthreads();
    float acc = ob[t];
    #pragma unroll 8
    for(int f = 0; f < 64; f++)
        acc = fmaf(p[f], oW[f*128 + t], acc);
    out[g*128 + t] = acc;
}

// ---------------- launch ----------------------------------------------------------------
extern "C" void kernel_launch(void* const* d_in, const int* in_sizes, int n_in,
                              void* d_out, int out_size){
    const float* x    = (const float*)d_in[0];
    const int*   ei   = (const int*)  d_in[1];
    const float* ea   = (const float*)d_in[2];
    const int*   batch= (const int*)  d_in[3];
    const float* lns  = (const float*)d_in[4];
    const float* lnb  = (const float*)d_in[5];
    const float* W1   = (const float*)d_in[6];
    const float* b1   = (const float*)d_in[7];
    const float* W2   = (const float*)d_in[8];
    const float* b2   = (const float*)d_in[9];
    const float* root = (const float*)d_in[10];
    const float* cb   = (const float*)d_in[11];
    const float* dW   = (const float*)d_in[12];
    const float* db   = (const float*)d_in[13];
    const float* oW   = (const float*)d_in[14];
    const float* ob   = (const float*)d_in[15];
    float* out = (float*)d_out;

    dim3 gq(Nn/128, Hh/8);   // 128 x 16 = 2048 CTAs of 128 threads

    // Launch index 3 (ncu capture slot) = k_q_mma(layer 0).
    k_prep<<<(Ne*Dd + 255)/256, 256>>>(W2, W1, ea);            // 0
    k_init<<<(Nn*Dd + 255)/256, 256>>>(x);                     // 1
    k_ln<<<Nn/8, 256>>>(lns, lnb);                             // 2
    k_q_mma<<<gq, 128>>>(0);                                   // 3  <- profiled
    k_degcnt<<<(Ne + 255)/256, 256>>>(ei, batch);              // 4
    k_scan<<<1, 1024>>>();                                     // 5
    k_fill<<<(Ne + 255)/256, 256>>>(ei);                       // 6
    k_emlp_mma<<<Ne/128, 256>>>(0, b1);                        // 7
    k_nn64<<<Nn/64, 256>>>(b2, nullptr, nullptr, nullptr, 0);  // 8: y2 = h@B2
    k_msg2<<<Nn/2, 64>>>();                                    // 9
    k_nn64<<<Nn/64, 256>>>(root, nullptr, cb, nullptr, 1);     // 10

    for(int l = 1; l < Ll; l++){
        k_ln<<<Nn/8, 256>>>(lns + l*64, lnb + l*64);
        k_emlp_mma<<<Ne/128, 256>>>(l, b1 + (size_t)l*128);
        k_nn64<<<Nn/64, 256>>>(b2 + (size_t)l*4096, nullptr, nullptr, nullptr, 0);
        k_q_mma<<<gq, 128>>>(l);
        k_msg2<<<Nn/2, 64>>>();
        k_nn64<<<Nn/64, 256>>>(root + (size_t)l*4096, nullptr, cb + (size_t)l*64, nullptr, 1);
    }

    k_nn64<<<Nn/64, 256>>>(dW, db, nullptr, batch, 2);  // dense + pool
    k_out<<<Gg, 128>>>(oW, ob, out);
}